// round 1
// baseline (speedup 1.0000x reference)
#include <cuda_runtime.h>

// BatchBlur: per-pixel 19x19 blur, reflection padding, weights shared across C=3.
//   input : (2, 3, 256, 256) f32
//   kernel: (2, 65536, 19, 19) f32   <-- 189 MB, streamed once (the bottleneck)
//   out   : (2, 3, 256, 256) f32 = sum_taps(patch * w) / 361
//
// Strategy: warp-per-pixel. Lanes cover the 361 taps -> weight loads are fully
// coalesced (consecutive lanes read consecutive floats of one pixel's kernel).
// 8 warps/block = 8 adjacent pixels in a row share a 19x26x3 smem input patch.

#define Bv 2
#define Cc 3
#define Hh 256
#define Ww 256
#define Lk 19
#define K2 361            // 19*19
#define PADK 9
#define PPB 8             // pixels per block (one row segment)
#define TPB 256
#define PATCH_W (PPB + Lk - 1)            // 26
#define PATCH_CH (Lk * PATCH_W)           // 494 floats per channel
#define PATCH_ELEMS (Cc * PATCH_CH)       // 1482

__global__ __launch_bounds__(TPB)
void batchblur_warp_kernel(const float* __restrict__ inp,
                           const float* __restrict__ kern,
                           float* __restrict__ out)
{
    __shared__ float s[PATCH_ELEMS];

    const int tid = threadIdx.x;
    const int blk = blockIdx.x;
    const int b   = blk >> 13;            // / (256 rows * 32 blocks-per-row)
    const int rem = blk & 8191;
    const int row = rem >> 5;             // / 32
    const int x0  = (rem & 31) * PPB;

    // ---- stage reflected input patch: rows [row-9, row+9], cols [x0-9, x0+16]
    const float* inb = inp + (size_t)b * (Cc * Hh * Ww);
    #pragma unroll 2
    for (int i = tid; i < PATCH_ELEMS; i += TPB) {
        int c  = i / PATCH_CH;
        int r2 = i - c * PATCH_CH;
        int r  = r2 / PATCH_W;
        int col = r2 - r * PATCH_W;
        int y = row + r - PADK;
        y = (y < 0) ? -y : ((y >= Hh) ? (2 * Hh - 2 - y) : y);
        int x = x0 + col - PADK;
        x = (x < 0) ? -x : ((x >= Ww) ? (2 * Ww - 2 - x) : x);
        s[i] = __ldg(inb + (c * Hh + y) * Ww + x);
    }
    __syncthreads();

    // ---- warp-per-pixel accumulation over 361 taps
    const int wid  = tid >> 5;
    const int lane = tid & 31;
    const int p    = (row << 8) + x0 + wid;             // pixel index 0..65535
    const float* wbase = kern + ((size_t)b * (Hh * Ww) + (size_t)p) * K2;

    float a0 = 0.f, a1 = 0.f, a2 = 0.f;
    #pragma unroll
    for (int i = 0; i < 12; i++) {
        int idx = i * 32 + lane;
        if (idx < K2) {
            float w  = __ldcs(wbase + idx);             // streaming: no L2 pollution
            int ki   = idx / Lk;
            int kj   = idx - ki * Lk;
            int soff = ki * PATCH_W + wid + kj;
            a0 += w * s[soff];
            a1 += w * s[PATCH_CH + soff];
            a2 += w * s[2 * PATCH_CH + soff];
        }
    }

    // ---- warp reduction (3 channels)
    #pragma unroll
    for (int o = 16; o > 0; o >>= 1) {
        a0 += __shfl_xor_sync(0xffffffffu, a0, o);
        a1 += __shfl_xor_sync(0xffffffffu, a1, o);
        a2 += __shfl_xor_sync(0xffffffffu, a2, o);
    }

    if (lane == 0) {
        const float inv = 1.0f / 361.0f;
        float* ob = out + (size_t)b * (Cc * Hh * Ww) + p;
        ob[0]            = a0 * inv;
        ob[Hh * Ww]      = a1 * inv;
        ob[2 * Hh * Ww]  = a2 * inv;
    }
}

extern "C" void kernel_launch(void* const* d_in, const int* in_sizes, int n_in,
                              void* d_out, int out_size)
{
    const float* inp  = (const float*)d_in[0];
    const float* kern = (const float*)d_in[1];
    // Defensive: identify the big per-pixel kernel tensor by size.
    if (n_in >= 2 && in_sizes[0] > in_sizes[1]) {
        inp  = (const float*)d_in[1];
        kern = (const float*)d_in[0];
    }
    const int grid = Bv * Hh * (Ww / PPB);   // 2*256*32 = 16384 blocks
    batchblur_warp_kernel<<<grid, TPB>>>(inp, kern, (float*)d_out);
}